// round 12
// baseline (speedup 1.0000x reference)
#include <cuda_runtime.h>
#include <cuda_fp16.h>
#include <math.h>
#include <stdint.h>

#define NN   40960
#define SS   4096
#define EE   81920
#define DD   64
#define HH   100
#define FIN  321
#define VV   50000

// ---------------- scratch (device globals; no allocation allowed) ----------------
__device__ float    g_h[NN * HH];
__device__ float    g_msg[NN * HH];
__device__ float    g_gi[NN * 3 * HH];
__device__ float    g_gh[NN * 3 * HH];
__device__ int      g_deg[NN];
__device__ float    g_dinv[NN];
__device__ int      g_lastidx[SS];
__device__ float    g_last[SS * HH];
__device__ float    g_g1[NN * HH];
__device__ float    g_gate[NN];
__device__ float    g_w[NN];
__device__ unsigned g_gmax[SS];
__device__ float    g_wsum[SS];
__device__ float    g_pooled[SS * HH];
// precompute tables: rows x 200 (cols 0..99 = W_msg path, 100..199 = W_last path)
#define T_CAT_OFF   0
#define T_SUB_OFF   256
#define T_ELEM_OFF  1280
#define T_BRAND_OFF 3328
#define T_SMALL_ROWS 7424
__device__ float    g_Tsmall[T_SMALL_ROWS * 200];
__device__ float    g_Titem[VV * 200];
__device__ float    g_W2[5 * 64 * 200];      // [seg][k][c]

// ---------------- f32x2 packed-math helpers (Blackwell FFMA2) ----------------
__device__ __forceinline__ unsigned long long f2_pack(float lo, float hi) {
    unsigned long long r;
    asm("mov.b64 %0, {%1, %2};" : "=l"(r) : "f"(lo), "f"(hi));
    return r;
}
__device__ __forceinline__ float2 f2_unpack(unsigned long long v) {
    float lo, hi;
    asm("mov.b64 {%0, %1}, %2;" : "=f"(lo), "=f"(hi) : "l"(v));
    return make_float2(lo, hi);
}
__device__ __forceinline__ unsigned long long f2_fma(unsigned long long a,
                                                     unsigned long long b,
                                                     unsigned long long c) {
    asm("fma.rn.f32x2 %0, %1, %2, %3;" : "=l"(c) : "l"(a), "l"(b), "l"(c));
    return c;
}

// ---------------- fp16 mma.sync (plain HMMA path) ----------------
__device__ __forceinline__ void mma_16n8k16_f16(float* d,
                                                const uint32_t* a, const uint32_t* b) {
    asm volatile(
        "mma.sync.aligned.m16n8k16.row.col.f32.f16.f16.f32 "
        "{%0, %1, %2, %3}, {%4, %5, %6, %7}, {%8, %9}, {%0, %1, %2, %3};"
        : "+f"(d[0]), "+f"(d[1]), "+f"(d[2]), "+f"(d[3])
        : "r"(a[0]), "r"(a[1]), "r"(a[2]), "r"(a[3]), "r"(b[0]), "r"(b[1]));
}

// ---------------- helpers ----------------
__device__ __forceinline__ unsigned enc_f(float f) {
    unsigned u = __float_as_uint(f);
    return (u & 0x80000000u) ? ~u : (u | 0x80000000u);
}
__device__ __forceinline__ float dec_f(unsigned e) {
    return (e & 0x80000000u) ? __uint_as_float(e ^ 0x80000000u) : __uint_as_float(~e);
}
__device__ __forceinline__ float fast_sigmoid(float x) {
    return 1.f / (1.f + __expf(-x));
}
__device__ __forceinline__ float fast_tanh(float x) {
    float t = __expf(-2.f * fabsf(x));
    float y = (1.f - t) / (1.f + t);
    return copysignf(y, x);
}

// ---------------- init / zero ----------------
__global__ void k_init_small() {
    int i = blockIdx.x * blockDim.x + threadIdx.x;
    if (i < NN) g_deg[i] = 0;
    if (i < SS) { g_lastidx[i] = -1; g_gmax[i] = 0u; g_wsum[i] = 0.f; }
}
__global__ void k_zero_big() {
    int i = blockIdx.x * blockDim.x + threadIdx.x;
    if (i < NN * HH) g_msg[i] = 0.f;
    if (i < SS * HH) g_pooled[i] = 0.f;
}

// ---------------- build concat weight slices W2[s] = [W_msg_seg | W_last_seg] ----------------
__global__ void k_build_w2(const float* __restrict__ W_msg,
                           const float* __restrict__ W_last) {
    int i = blockIdx.x * blockDim.x + threadIdx.x;
    if (i >= 5 * 64 * 200) return;
    int s = i / 12800, rem = i - s * 12800;
    int k = rem / 200, c = rem - k * 200;
    int row = 1 + 64 * s + k;
    g_W2[i] = (c < HH) ? W_msg[row * HH + c] : W_last[row * HH + (c - HH)];
}

// ---------------- tiled SGEMM: C = A[M,K] @ B[K,Nn] (+bias) (+relu) ----------------
// 128x64 block tile, 8x4 per-thread register tile, f32x2 packed FMA.
__global__ void k_sgemm(const float* __restrict__ A, const float* __restrict__ B,
                        const float* __restrict__ bias, float* __restrict__ C,
                        int M, int Nn, int K, int relu) {
    __shared__ float As[128][17];
    __shared__ float Bs[16][64];
    int tid = threadIdx.x;
    int tx = tid & 15, ty = tid >> 4;
    int m0 = blockIdx.y * 128, n0 = blockIdx.x * 64;

    unsigned long long acc2[8][2];
#pragma unroll
    for (int i = 0; i < 8; i++) { acc2[i][0] = 0ull; acc2[i][1] = 0ull; }

    for (int k0 = 0; k0 < K; k0 += 16) {
        for (int i = tid; i < 128 * 16; i += 256) {
            int mi = i >> 4, ki = i & 15;
            int m = m0 + mi, k = k0 + ki;
            As[mi][ki] = (m < M && k < K) ? A[(size_t)m * K + k] : 0.f;
        }
        for (int i = tid; i < 16 * 64; i += 256) {
            int ki = i >> 6, ni = i & 63;
            int k = k0 + ki, n = n0 + ni;
            Bs[ki][ni] = (k < K && n < Nn) ? B[(size_t)k * Nn + n] : 0.f;
        }
        __syncthreads();
#pragma unroll
        for (int k = 0; k < 16; k++) {
            ulonglong2 b2 = *(const ulonglong2*)&Bs[k][tx * 4];
#pragma unroll
            for (int i = 0; i < 8; i++) {
                float a = As[ty * 8 + i][k];
                unsigned long long ap = f2_pack(a, a);
                acc2[i][0] = f2_fma(ap, b2.x, acc2[i][0]);
                acc2[i][1] = f2_fma(ap, b2.y, acc2[i][1]);
            }
        }
        __syncthreads();
    }

#pragma unroll
    for (int i = 0; i < 8; i++) {
        int m = m0 + ty * 8 + i;
        if (m >= M) continue;
        float2 p0 = f2_unpack(acc2[i][0]);
        float2 p1 = f2_unpack(acc2[i][1]);
        float vals[4] = {p0.x, p0.y, p1.x, p1.y};
#pragma unroll
        for (int j = 0; j < 4; j++) {
            int n = n0 + tx * 4 + j;
            if (n >= Nn) continue;
            float v = vals[j];
            if (bias) v += bias[n];
            if (relu) v = fmaxf(v, 0.f);
            C[(size_t)m * Nn + n] = v;
        }
    }
}

// ---------------- h0 gather-add: h0 = price*W0 + 5 table rows + b_msg ----------------
__global__ void k_build_h0(const float* __restrict__ price,
                           const int* __restrict__ cat, const int* __restrict__ sub,
                           const int* __restrict__ elem, const int* __restrict__ brand,
                           const int* __restrict__ pid,
                           const float* __restrict__ W_msg,   // row 0 = price weights
                           const float* __restrict__ b_msg) {
    int n = blockIdx.x;
    int j = threadIdx.x;
    if (j >= HH) return;
    float v = price[n] * W_msg[j] + b_msg[j]
            + g_Tsmall[(T_CAT_OFF   + cat[n])   * 200 + j]
            + g_Tsmall[(T_SUB_OFF   + sub[n])   * 200 + j]
            + g_Tsmall[(T_ELEM_OFF  + elem[n])  * 200 + j]
            + g_Tsmall[(T_BRAND_OFF + brand[n]) * 200 + j]
            + g_Titem[(size_t)pid[n] * 200 + j];
    g_h[n * HH + j] = v;
}

// ---------------- last-node features per session (tables, cols 100..199) ----------------
__global__ void k_build_last(const float* __restrict__ price,
                             const int* __restrict__ cat, const int* __restrict__ sub,
                             const int* __restrict__ elem, const int* __restrict__ brand,
                             const int* __restrict__ pid,
                             const float* __restrict__ W_last,  // row 0 = price weights
                             const float* __restrict__ b_last) {
    int s = blockIdx.x;
    int j = threadIdx.x;
    if (j >= HH) return;
    int n = g_lastidx[s];
    float v = price[n] * W_last[j] + b_last[j]
            + g_Tsmall[(T_CAT_OFF   + cat[n])   * 200 + 100 + j]
            + g_Tsmall[(T_SUB_OFF   + sub[n])   * 200 + 100 + j]
            + g_Tsmall[(T_ELEM_OFF  + elem[n])  * 200 + 100 + j]
            + g_Tsmall[(T_BRAND_OFF + brand[n]) * 200 + 100 + j]
            + g_Titem[(size_t)pid[n] * 200 + 100 + j];
    g_last[s * HH + j] = v;
}

// ---------------- degree + inverse ----------------
__global__ void k_deg(const int* __restrict__ eidx) {
    int e = blockIdx.x * blockDim.x + threadIdx.x;
    if (e < EE) atomicAdd(&g_deg[eidx[EE + e]], 1);
}
__global__ void k_dinv() {
    int n = blockIdx.x * blockDim.x + threadIdx.x;
    if (n < NN) g_dinv[n] = (g_deg[n] > 0) ? (1.f / (float)g_deg[n]) : 0.f;
}

// ---------------- edge scatter: msg[dst] += h[src] (flattened) ----------------
__global__ void k_scatter(const int* __restrict__ eidx) {
    int i = blockIdx.x * blockDim.x + threadIdx.x;
    if (i >= EE * HH) return;
    int e = i / HH, d = i - e * HH;
    int s = eidx[e];
    int t = eidx[EE + e];
    atomicAdd(&g_msg[t * HH + d], g_h[s * HH + d]);
}
__global__ void k_scale_msg() {
    int i = blockIdx.x * blockDim.x + threadIdx.x;
    if (i < NN * HH) g_msg[i] *= g_dinv[i / HH];
}

// ---------------- GRU cell elementwise ----------------
__global__ void k_gru() {
    int i = blockIdx.x * blockDim.x + threadIdx.x;
    if (i >= NN * HH) return;
    int n = i / HH, j = i % HH;
    const float* gi = g_gi + n * 3 * HH;
    const float* gh = g_gh + n * 3 * HH;
    float r  = fast_sigmoid(gi[j] + gh[j]);
    float z  = fast_sigmoid(gi[HH + j] + gh[HH + j]);
    float nn = fast_tanh(gi[2 * HH + j] + r * gh[2 * HH + j]);
    float h  = g_h[i];
    g_h[i] = (1.f - z) * nn + z * h;
}

// ---------------- last index per session ----------------
__global__ void k_lastidx(const int* __restrict__ batch) {
    int n = blockIdx.x * blockDim.x + threadIdx.x;
    if (n < NN) atomicMax(&g_lastidx[batch[n]], n);
}
__global__ void k_addlast(const int* __restrict__ batch) {
    int i = blockIdx.x * blockDim.x + threadIdx.x;
    if (i >= NN * HH) return;
    g_h[i] += g_last[batch[i / HH] * HH + i % HH];
}

// ---------------- attention gate ----------------
__global__ void k_gate(const float* __restrict__ wg2, const float* __restrict__ bg2,
                       const int* __restrict__ batch) {
    int w = (blockIdx.x * blockDim.x + threadIdx.x) >> 5;
    int lane = threadIdx.x & 31;
    if (w >= NN) return;
    const float* row = g_g1 + w * HH;
    float s = 0.f;
    for (int k = lane; k < HH; k += 32) s += row[k] * wg2[k];
#pragma unroll
    for (int o = 16; o; o >>= 1) s += __shfl_xor_sync(0xffffffffu, s, o);
    if (lane == 0) {
        float g = s + bg2[0];
        g_gate[w] = g;
        atomicMax(&g_gmax[batch[w]], enc_f(g));
    }
}
__global__ void k_softw(const int* __restrict__ batch) {
    int n = blockIdx.x * blockDim.x + threadIdx.x;
    if (n >= NN) return;
    int b = batch[n];
    float wv = __expf(g_gate[n] - dec_f(g_gmax[b]));
    g_w[n] = wv;
    atomicAdd(&g_wsum[b], wv);
}
__global__ void k_pool(const int* __restrict__ batch) {
    int i = blockIdx.x * blockDim.x + threadIdx.x;
    if (i >= NN * HH) return;
    int n = i / HH, d = i - n * HH;
    int b = batch[n];
    float alpha = g_w[n] / g_wsum[b];
    atomicAdd(&g_pooled[b * HH + d], alpha * g_h[i]);
}

// ================= FC via fp16 mma.sync m16n8k16 (native HMMA path) =================
#define FKH 120
#define FC_SMEM_H (128 * FKH * 2 * 2 + 512)   /* 61952 bytes */

__global__ void __launch_bounds__(256)
k_fc(const float* __restrict__ pooled, const float* __restrict__ W,
     const float* __restrict__ bias, float* __restrict__ C) {
    extern __shared__ __align__(16) char smraw[];
    __half*   BsH  = (__half*)smraw;
    uint32_t* Bs32 = (uint32_t*)smraw;
    uint32_t* As32 = (uint32_t*)(smraw + 128 * FKH * 2);
    float*    biasS = (float*)(smraw + 2 * 128 * FKH * 2);
    int tid = threadIdx.x;
    int lane = tid & 31, wid = tid >> 5;
    int n0 = blockIdx.x * 128;
    int m_begin = blockIdx.y * 16;

    for (int i = tid; i < 2 * 128 * (FKH / 2); i += 256) ((uint32_t*)smraw)[i] = 0u;
    if (tid < 128) biasS[tid] = (n0 + tid < VV) ? bias[n0 + tid] : 0.f;
    __syncthreads();

    for (int i = tid; i < HH * 128; i += 256) {
        int k = i >> 7, n = i & 127;
        int gn = n0 + n;
        if (gn < VV) BsH[n * FKH + k] = __float2half_rn(W[(size_t)k * VV + gn]);
    }

    int wm = wid >> 2, wn = wid & 3;
    int g = lane >> 2, tg = lane & 3;

    for (int it = 0; it < 16; it++) {
        int m0 = (m_begin + it) * 128;
        for (int p = tid; p < 128 * (HH / 2); p += 256) {
            int r = p / (HH / 2), kp = p - r * (HH / 2);
            float2 v = *(const float2*)&pooled[(size_t)(m0 + r) * HH + 2 * kp];
            __half2 h2 = __floats2half2_rn(v.x, v.y);
            As32[r * (FKH / 2) + kp] = *(uint32_t*)&h2;
        }
        __syncthreads();

        float acc[4][4][4];
#pragma unroll
        for (int mi = 0; mi < 4; mi++)
#pragma unroll
            for (int ni = 0; ni < 4; ni++)
#pragma unroll
                for (int j = 0; j < 4; j++) acc[mi][ni][j] = 0.f;

#pragma unroll
        for (int ks = 0; ks < 7; ks++) {
            int kw = ks * 8;
            uint32_t af[4][4], bf[4][2];
#pragma unroll
            for (int mi = 0; mi < 4; mi++) {
                int r0 = wm * 64 + mi * 16 + g;
                const uint32_t* ap = &As32[r0 * 60 + kw + tg];
                af[mi][0] = ap[0];
                af[mi][1] = ap[8 * 60];
                af[mi][2] = ap[4];
                af[mi][3] = ap[8 * 60 + 4];
            }
#pragma unroll
            for (int ni = 0; ni < 4; ni++) {
                int nb = wn * 32 + ni * 8 + g;
                const uint32_t* bp = &Bs32[nb * 60 + kw + tg];
                bf[ni][0] = bp[0];
                bf[ni][1] = bp[4];
            }
#pragma unroll
            for (int mi = 0; mi < 4; mi++)
#pragma unroll
                for (int ni = 0; ni < 4; ni++)
                    mma_16n8k16_f16(acc[mi][ni], af[mi], bf[ni]);
        }

#pragma unroll
        for (int mi = 0; mi < 4; mi++) {
            int r = m0 + wm * 64 + mi * 16 + g;
            size_t rb0 = (size_t)r * VV;
            size_t rb1 = (size_t)(r + 8) * VV;
#pragma unroll
            for (int ni = 0; ni < 4; ni++) {
                int cn = wn * 32 + ni * 8 + 2 * tg;
                int gn = n0 + cn;
                if (gn < VV) {
                    float bx = biasS[cn], by = biasS[cn + 1];
                    *(float2*)&C[rb0 + gn] = make_float2(acc[mi][ni][0] + bx,
                                                         acc[mi][ni][1] + by);
                    *(float2*)&C[rb1 + gn] = make_float2(acc[mi][ni][2] + bx,
                                                         acc[mi][ni][3] + by);
                }
            }
        }
        __syncthreads();
    }
}

// ---------------- launch ----------------
extern "C" void kernel_launch(void* const* d_in, const int* in_sizes, int n_in,
                              void* d_out, int out_size) {
    const float* price    = (const float*)d_in[0];
    const int*   category = (const int*)d_in[1];
    const int*   sub      = (const int*)d_in[2];
    const int*   elem     = (const int*)d_in[3];
    const int*   brand    = (const int*)d_in[4];
    const int*   pid      = (const int*)d_in[5];
    const int*   eidx     = (const int*)d_in[6];
    const int*   batch    = (const int*)d_in[7];
    const float* ecat     = (const float*)d_in[8];
    const float* esub     = (const float*)d_in[9];
    const float* eelem    = (const float*)d_in[10];
    const float* ebrand   = (const float*)d_in[11];
    const float* eitem    = (const float*)d_in[12];
    const float* W_msg    = (const float*)d_in[13];
    const float* b_msg    = (const float*)d_in[14];
    const float* W_ih     = (const float*)d_in[15];
    const float* W_hh     = (const float*)d_in[16];
    const float* b_ih     = (const float*)d_in[17];
    const float* b_hh     = (const float*)d_in[18];
    const float* W_last   = (const float*)d_in[19];
    const float* b_last   = (const float*)d_in[20];
    const float* W_g1     = (const float*)d_in[21];
    const float* b_g1     = (const float*)d_in[22];
    const float* W_g2     = (const float*)d_in[23];
    const float* b_g2     = (const float*)d_in[24];
    const float* W_fc     = (const float*)d_in[25];
    const float* b_fc     = (const float*)d_in[26];
    float* out = (float*)d_out;

    float *p_h, *p_msg, *p_gi, *p_gh, *p_g1, *p_pooled, *p_Tsmall, *p_Titem, *p_W2;
    cudaGetSymbolAddress((void**)&p_h,      g_h);
    cudaGetSymbolAddress((void**)&p_msg,    g_msg);
    cudaGetSymbolAddress((void**)&p_gi,     g_gi);
    cudaGetSymbolAddress((void**)&p_gh,     g_gh);
    cudaGetSymbolAddress((void**)&p_g1,     g_g1);
    cudaGetSymbolAddress((void**)&p_pooled, g_pooled);
    cudaGetSymbolAddress((void**)&p_Tsmall, g_Tsmall);
    cudaGetSymbolAddress((void**)&p_Titem,  g_Titem);
    cudaGetSymbolAddress((void**)&p_W2,     g_W2);

    cudaFuncSetAttribute(k_fc, cudaFuncAttributeMaxDynamicSharedMemorySize, FC_SMEM_H);

    // init scratch
    k_init_small<<<(NN + 255) / 256, 256>>>();
    k_zero_big<<<(NN * HH + 255) / 256, 256>>>();
    k_lastidx<<<(NN + 255) / 256, 256>>>(batch);

    // build concat weight slices, then precompute embedding@weight tables
    k_build_w2<<<(5 * 64 * 200 + 255) / 256, 256>>>(W_msg, W_last);
    {
        dim3 gn(4, 2);    // N=200 -> 4 tiles of 64
        k_sgemm<<<dim3(4, (256 + 127) / 128),  256>>>(ecat,   p_W2 + 0 * 12800, nullptr, p_Tsmall + T_CAT_OFF   * 200, 256,  200, 64, 0);
        k_sgemm<<<dim3(4, (1024 + 127) / 128), 256>>>(esub,   p_W2 + 1 * 12800, nullptr, p_Tsmall + T_SUB_OFF   * 200, 1024, 200, 64, 0);
        k_sgemm<<<dim3(4, (2048 + 127) / 128), 256>>>(eelem,  p_W2 + 2 * 12800, nullptr, p_Tsmall + T_ELEM_OFF  * 200, 2048, 200, 64, 0);
        k_sgemm<<<dim3(4, (4096 + 127) / 128), 256>>>(ebrand, p_W2 + 3 * 12800, nullptr, p_Tsmall + T_BRAND_OFF * 200, 4096, 200, 64, 0);
        k_sgemm<<<dim3(4, (VV + 127) / 128),   256>>>(eitem,  p_W2 + 4 * 12800, nullptr, p_Titem,                      VV,   200, 64, 0);
    }

    // h0 via gather-add (replaces x build + W_msg GEMM)
    k_build_h0<<<NN, 128>>>(price, category, sub, elem, brand, pid, W_msg, b_msg);

    // degrees
    k_deg<<<(EE + 255) / 256, 256>>>(eidx);
    k_dinv<<<(NN + 255) / 256, 256>>>();

    // mean aggregation
    k_scatter<<<(EE * HH + 255) / 256, 256>>>(eidx);
    k_scale_msg<<<(NN * HH + 255) / 256, 256>>>();

    // GRU gates (f32x2 SGEMM — proven config)
    {
        dim3 g((3 * HH + 63) / 64, (NN + 127) / 128);
        k_sgemm<<<g, 256>>>(p_msg, W_ih, b_ih, p_gi, NN, 3 * HH, HH, 0);
        k_sgemm<<<g, 256>>>(p_h,   W_hh, b_hh, p_gh, NN, 3 * HH, HH, 0);
    }
    k_gru<<<(NN * HH + 255) / 256, 256>>>();

    // last-node contribution via tables (replaces x_last gather + W_last GEMM)
    k_build_last<<<SS, 128>>>(price, category, sub, elem, brand, pid, W_last, b_last);
    k_addlast<<<(NN * HH + 255) / 256, 256>>>(batch);

    // attention gate MLP
    {
        dim3 g((HH + 63) / 64, (NN + 127) / 128);
        k_sgemm<<<g, 256>>>(p_h, W_g1, b_g1, p_g1, NN, HH, HH, 1);
    }
    k_gate<<<(NN * 32 + 255) / 256, 256>>>(W_g2, b_g2, batch);
    k_softw<<<(NN + 255) / 256, 256>>>(batch);
    k_pool<<<(NN * HH + 255) / 256, 256>>>(batch);

    // final scoring: fp16 mma.sync m16n8k16
    {
        dim3 g((VV + 127) / 128, 2);
        k_fc<<<g, 256, FC_SMEM_H>>>(p_pooled, W_fc, b_fc, out);
    }
}

// round 13
// speedup vs baseline: 1.0004x; 1.0004x over previous
#include <cuda_runtime.h>
#include <cuda_fp16.h>
#include <math.h>
#include <stdint.h>

#define NN   40960
#define SS   4096
#define EE   81920
#define DD   64
#define HH   100
#define FIN  321
#define VV   50000

// ---------------- scratch (device globals; no allocation allowed) ----------------
__device__ float    g_x[NN * FIN];
__device__ float    g_xl[SS * FIN];
__device__ float    g_h[NN * HH];
__device__ float    g_msg[NN * HH];
__device__ float    g_gi[NN * 3 * HH];
__device__ float    g_gh[NN * 3 * HH];
__device__ int      g_deg[NN];
__device__ float    g_dinv[NN];
__device__ int      g_lastidx[SS];
__device__ float    g_last[SS * HH];
__device__ float    g_g1[NN * HH];
__device__ float    g_gate[NN];
__device__ float    g_w[NN];
__device__ unsigned g_gmax[SS];
__device__ float    g_wsum[SS];
__device__ float    g_pooled[SS * HH];

// ---------------- f32x2 packed-math helpers (Blackwell FFMA2) ----------------
__device__ __forceinline__ unsigned long long f2_pack(float lo, float hi) {
    unsigned long long r;
    asm("mov.b64 %0, {%1, %2};" : "=l"(r) : "f"(lo), "f"(hi));
    return r;
}
__device__ __forceinline__ float2 f2_unpack(unsigned long long v) {
    float lo, hi;
    asm("mov.b64 {%0, %1}, %2;" : "=f"(lo), "=f"(hi) : "l"(v));
    return make_float2(lo, hi);
}
__device__ __forceinline__ unsigned long long f2_fma(unsigned long long a,
                                                     unsigned long long b,
                                                     unsigned long long c) {
    asm("fma.rn.f32x2 %0, %1, %2, %3;" : "=l"(c) : "l"(a), "l"(b), "l"(c));
    return c;
}

// ---------------- fp16 mma.sync (plain HMMA path) ----------------
__device__ __forceinline__ void mma_16n8k16_f16(float* d,
                                                const uint32_t* a, const uint32_t* b) {
    asm volatile(
        "mma.sync.aligned.m16n8k16.row.col.f32.f16.f16.f32 "
        "{%0, %1, %2, %3}, {%4, %5, %6, %7}, {%8, %9}, {%0, %1, %2, %3};"
        : "+f"(d[0]), "+f"(d[1]), "+f"(d[2]), "+f"(d[3])
        : "r"(a[0]), "r"(a[1]), "r"(a[2]), "r"(a[3]), "r"(b[0]), "r"(b[1]));
}

// ---------------- helpers ----------------
__device__ __forceinline__ unsigned enc_f(float f) {
    unsigned u = __float_as_uint(f);
    return (u & 0x80000000u) ? ~u : (u | 0x80000000u);
}
__device__ __forceinline__ float dec_f(unsigned e) {
    return (e & 0x80000000u) ? __uint_as_float(e ^ 0x80000000u) : __uint_as_float(~e);
}
__device__ __forceinline__ float fast_sigmoid(float x) {
    return 1.f / (1.f + __expf(-x));
}
__device__ __forceinline__ float fast_tanh(float x) {
    float t = __expf(-2.f * fabsf(x));
    float y = (1.f - t) / (1.f + t);
    return copysignf(y, x);
}
// split v into fp16 hi + fp16 lo pair words
__device__ __forceinline__ void split_pack(float v0, float v1,
                                           uint32_t& whi, uint32_t& wlo) {
    __half h0 = __float2half_rn(v0), h1 = __float2half_rn(v1);
    float  l0 = v0 - __half2float(h0), l1 = v1 - __half2float(h1);
    __half2 hh = __halves2half2(h0, h1);
    __half2 ll = __floats2half2_rn(l0, l1);
    whi = *(uint32_t*)&hh;
    wlo = *(uint32_t*)&ll;
}

// ---------------- init / zero ----------------
__global__ void k_init_small() {
    int i = blockIdx.x * blockDim.x + threadIdx.x;
    if (i < NN) g_deg[i] = 0;
    if (i < SS) { g_lastidx[i] = -1; g_gmax[i] = 0u; g_wsum[i] = 0.f; }
}
__global__ void k_zero_big() {
    int i = blockIdx.x * blockDim.x + threadIdx.x;
    if (i < NN * HH) g_msg[i] = 0.f;
    if (i < SS * HH) g_pooled[i] = 0.f;
}

// ---------------- node feature gather: x[n, 0..320] ----------------
__global__ void k_gather_x(const float* __restrict__ price,
                           const int* __restrict__ cat, const int* __restrict__ sub,
                           const int* __restrict__ elem, const int* __restrict__ brand,
                           const int* __restrict__ pid,
                           const float* __restrict__ ecat, const float* __restrict__ esub,
                           const float* __restrict__ eelem, const float* __restrict__ ebrand,
                           const float* __restrict__ eitem) {
    int n = blockIdx.x;
    int j = threadIdx.x;
    if (j >= FIN) return;
    float v;
    if (j == 0) {
        v = price[n];
    } else {
        int s = (j - 1) >> 6;
        int o = (j - 1) & 63;
        const float* tab;
        int idx;
        switch (s) {
            case 0:  tab = ecat;   idx = cat[n];   break;
            case 1:  tab = esub;   idx = sub[n];   break;
            case 2:  tab = eelem;  idx = elem[n];  break;
            case 3:  tab = ebrand; idx = brand[n]; break;
            default: tab = eitem;  idx = pid[n];   break;
        }
        v = tab[idx * DD + o];
    }
    g_x[n * FIN + j] = v;
}

// ---------------- tiled SGEMM: C = A[M,K] @ B[K,Nn] + bias, optional relu ----------------
// 128x64 block tile, 8x4 per-thread register tile, f32x2 packed FMA.
__global__ void k_sgemm(const float* __restrict__ A, const float* __restrict__ B,
                        const float* __restrict__ bias, float* __restrict__ C,
                        int M, int Nn, int K, int relu) {
    __shared__ float As[128][17];
    __shared__ float Bs[16][64];
    int tid = threadIdx.x;
    int tx = tid & 15, ty = tid >> 4;
    int m0 = blockIdx.y * 128, n0 = blockIdx.x * 64;

    unsigned long long acc2[8][2];
#pragma unroll
    for (int i = 0; i < 8; i++) { acc2[i][0] = 0ull; acc2[i][1] = 0ull; }

    for (int k0 = 0; k0 < K; k0 += 16) {
        for (int i = tid; i < 128 * 16; i += 256) {
            int mi = i >> 4, ki = i & 15;
            int m = m0 + mi, k = k0 + ki;
            As[mi][ki] = (m < M && k < K) ? A[(size_t)m * K + k] : 0.f;
        }
        for (int i = tid; i < 16 * 64; i += 256) {
            int ki = i >> 6, ni = i & 63;
            int k = k0 + ki, n = n0 + ni;
            Bs[ki][ni] = (k < K && n < Nn) ? B[(size_t)k * Nn + n] : 0.f;
        }
        __syncthreads();
#pragma unroll
        for (int k = 0; k < 16; k++) {
            ulonglong2 b2 = *(const ulonglong2*)&Bs[k][tx * 4];
#pragma unroll
            for (int i = 0; i < 8; i++) {
                float a = As[ty * 8 + i][k];
                unsigned long long ap = f2_pack(a, a);
                acc2[i][0] = f2_fma(ap, b2.x, acc2[i][0]);
                acc2[i][1] = f2_fma(ap, b2.y, acc2[i][1]);
            }
        }
        __syncthreads();
    }

#pragma unroll
    for (int i = 0; i < 8; i++) {
        int m = m0 + ty * 8 + i;
        if (m >= M) continue;
        float2 p0 = f2_unpack(acc2[i][0]);
        float2 p1 = f2_unpack(acc2[i][1]);
        float vals[4] = {p0.x, p0.y, p1.x, p1.y};
#pragma unroll
        for (int j = 0; j < 4; j++) {
            int n = n0 + tx * 4 + j;
            if (n >= Nn) continue;
            float v = vals[j] + bias[n];
            if (relu) v = fmaxf(v, 0.f);
            C[(size_t)m * Nn + n] = v;
        }
    }
}

// ========== k_hgemm2: split-fp16 HMMA GEMM for K <= 104 (k_fc-shaped) ==========
// C = A[M,K] @ B[K,Nn] + bias (+relu). 3-MMA split: AhBh + AhBl + AlBh.
// B panel: 128 N-cols x K, hi+lo, RESIDENT. A tile: 64 rows x K, hi+lo, per M-tile.
// Warp grid 2x4, warp tile 32x32. Grid-stride over M-tiles of 64 rows.
// Stride 60 words: fragment banks (28g + tg) mod 32 conflict-free.
#define H2STW 60
#define H2_SMEM ((2 * 128 * H2STW + 2 * 64 * H2STW + 128) * 4)   /* 94720 B */

__global__ void __launch_bounds__(256, 2)
k_hgemm2(const float* __restrict__ A, const float* __restrict__ B,
         const float* __restrict__ bias, float* __restrict__ C,
         int M, int Nn, int K, int relu) {
    extern __shared__ __align__(16) char smraw[];
    uint32_t* BsH = (uint32_t*)smraw;                 // [128][60]
    uint32_t* BsL = BsH + 128 * H2STW;
    uint32_t* AsH = BsL + 128 * H2STW;                // [64][60]
    uint32_t* AsL = AsH + 64 * H2STW;
    float* biasS  = (float*)(AsL + 64 * H2STW);
    int tid = threadIdx.x;
    int lane = tid & 31, wid = tid >> 5;
    int n0 = blockIdx.x * 128;
    int KW = (K + 1) >> 1;                            // valid word-cols (<=52)
    int ksteps = (K + 15) >> 4;

    // zero all smem word regions (pads persist as zero)
    for (int i = tid; i < 2 * 128 * H2STW + 2 * 64 * H2STW; i += 256)
        BsH[i] = 0u;
    if (tid < 128) biasS[tid] = (n0 + tid < Nn) ? bias[n0 + tid] : 0.f;
    __syncthreads();

    // load B panel: [n][k] transposed for .col; coalesced over n
    for (int i = tid; i < KW * 128; i += 256) {
        int kp = i >> 7, n = i & 127;
        int gn = n0 + n, gk = 2 * kp;
        if (gn < Nn) {
            float v0 = B[(size_t)gk * Nn + gn];
            float v1 = (gk + 1 < K) ? B[(size_t)(gk + 1) * Nn + gn] : 0.f;
            uint32_t whi, wlo;
            split_pack(v0, v1, whi, wlo);
            BsH[n * H2STW + kp] = whi;
            BsL[n * H2STW + kp] = wlo;
        }
    }
    __syncthreads();

    int wm = wid >> 2, wn = wid & 3;   // warp tile: rows wm*32, cols wn*32
    int g = lane >> 2, tg = lane & 3;

    for (int t = blockIdx.y; t * 64 < M; t += gridDim.y) {
        int m0 = t * 64;
        // load A tile: 64 rows x KW words, coalesced over k within row
        for (int i = tid; i < 64 * KW; i += 256) {
            int r = i / KW, kp = i - r * KW;
            int gk = 2 * kp;
            const float* ap = &A[(size_t)(m0 + r) * K + gk];
            float v0 = ap[0];
            float v1 = (gk + 1 < K) ? ap[1] : 0.f;
            uint32_t whi, wlo;
            split_pack(v0, v1, whi, wlo);
            AsH[r * H2STW + kp] = whi;
            AsL[r * H2STW + kp] = wlo;
        }
        __syncthreads();

        float acc[2][4][4];
#pragma unroll
        for (int mi = 0; mi < 2; mi++)
#pragma unroll
            for (int ni = 0; ni < 4; ni++)
#pragma unroll
                for (int j = 0; j < 4; j++) acc[mi][ni][j] = 0.f;

        for (int ks = 0; ks < ksteps; ks++) {
            int kw = ks * 8;
            uint32_t afH[2][4], afL[2][4], bfH[4][2], bfL[4][2];
#pragma unroll
            for (int mi = 0; mi < 2; mi++) {
                int r0 = wm * 32 + mi * 16 + g;
                const uint32_t* apH = &AsH[r0 * H2STW + kw + tg];
                const uint32_t* apL = &AsL[r0 * H2STW + kw + tg];
                afH[mi][0] = apH[0];              afH[mi][1] = apH[8 * H2STW];
                afH[mi][2] = apH[4];              afH[mi][3] = apH[8 * H2STW + 4];
                afL[mi][0] = apL[0];              afL[mi][1] = apL[8 * H2STW];
                afL[mi][2] = apL[4];              afL[mi][3] = apL[8 * H2STW + 4];
            }
#pragma unroll
            for (int ni = 0; ni < 4; ni++) {
                int nb = wn * 32 + ni * 8 + g;
                const uint32_t* bpH = &BsH[nb * H2STW + kw + tg];
                const uint32_t* bpL = &BsL[nb * H2STW + kw + tg];
                bfH[ni][0] = bpH[0];              bfH[ni][1] = bpH[4];
                bfL[ni][0] = bpL[0];              bfL[ni][1] = bpL[4];
            }
#pragma unroll
            for (int mi = 0; mi < 2; mi++)
#pragma unroll
                for (int ni = 0; ni < 4; ni++) {
                    mma_16n8k16_f16(acc[mi][ni], afH[mi], bfH[ni]);
                    mma_16n8k16_f16(acc[mi][ni], afH[mi], bfL[ni]);
                    mma_16n8k16_f16(acc[mi][ni], afL[mi], bfH[ni]);
                }
        }

        // epilogue (M multiple of 64; Nn even so pairs never straddle)
#pragma unroll
        for (int mi = 0; mi < 2; mi++) {
            int r = m0 + wm * 32 + mi * 16 + g;
            size_t rb0 = (size_t)r * Nn;
            size_t rb1 = (size_t)(r + 8) * Nn;
#pragma unroll
            for (int ni = 0; ni < 4; ni++) {
                int cn = wn * 32 + ni * 8 + 2 * tg;
                int gn = n0 + cn;
                if (gn < Nn) {
                    float bx = biasS[cn], by = biasS[cn + 1];
                    float v00 = acc[mi][ni][0] + bx, v01 = acc[mi][ni][1] + by;
                    float v10 = acc[mi][ni][2] + bx, v11 = acc[mi][ni][3] + by;
                    if (relu) {
                        v00 = fmaxf(v00, 0.f); v01 = fmaxf(v01, 0.f);
                        v10 = fmaxf(v10, 0.f); v11 = fmaxf(v11, 0.f);
                    }
                    *(float2*)&C[rb0 + gn] = make_float2(v00, v01);
                    *(float2*)&C[rb1 + gn] = make_float2(v10, v11);
                }
            }
        }
        __syncthreads();   // before next A tile overwrite
    }
}

// ---------------- degree + inverse ----------------
__global__ void k_deg(const int* __restrict__ eidx) {
    int e = blockIdx.x * blockDim.x + threadIdx.x;
    if (e < EE) atomicAdd(&g_deg[eidx[EE + e]], 1);
}
__global__ void k_dinv() {
    int n = blockIdx.x * blockDim.x + threadIdx.x;
    if (n < NN) g_dinv[n] = (g_deg[n] > 0) ? (1.f / (float)g_deg[n]) : 0.f;
}

// ---------------- edge scatter: msg[dst] += h[src] ----------------
__global__ void k_scatter(const int* __restrict__ eidx) {
    int e = blockIdx.x;
    int d = threadIdx.x;
    if (d >= HH) return;
    int s = eidx[e];
    int t = eidx[EE + e];
    atomicAdd(&g_msg[t * HH + d], g_h[s * HH + d]);
}
__global__ void k_scale_msg() {
    int i = blockIdx.x * blockDim.x + threadIdx.x;
    if (i < NN * HH) g_msg[i] *= g_dinv[i / HH];
}

// ---------------- GRU cell elementwise ----------------
__global__ void k_gru() {
    int i = blockIdx.x * blockDim.x + threadIdx.x;
    if (i >= NN * HH) return;
    int n = i / HH, j = i % HH;
    const float* gi = g_gi + n * 3 * HH;
    const float* gh = g_gh + n * 3 * HH;
    float r  = fast_sigmoid(gi[j] + gh[j]);
    float z  = fast_sigmoid(gi[HH + j] + gh[HH + j]);
    float nn = fast_tanh(gi[2 * HH + j] + r * gh[2 * HH + j]);
    float h  = g_h[i];
    g_h[i] = (1.f - z) * nn + z * h;
}

// ---------------- last index per session + gather ----------------
__global__ void k_lastidx(const int* __restrict__ batch) {
    int n = blockIdx.x * blockDim.x + threadIdx.x;
    if (n < NN) atomicMax(&g_lastidx[batch[n]], n);
}
__global__ void k_gather_xl() {
    int s = blockIdx.x;
    int j = threadIdx.x;
    if (j >= FIN) return;
    g_xl[s * FIN + j] = g_x[g_lastidx[s] * FIN + j];
}
__global__ void k_addlast(const int* __restrict__ batch) {
    int i = blockIdx.x * blockDim.x + threadIdx.x;
    if (i >= NN * HH) return;
    g_h[i] += g_last[batch[i / HH] * HH + i % HH];
}

// ---------------- attention gate ----------------
__global__ void k_gate(const float* __restrict__ wg2, const float* __restrict__ bg2,
                       const int* __restrict__ batch) {
    int w = (blockIdx.x * blockDim.x + threadIdx.x) >> 5;
    int lane = threadIdx.x & 31;
    if (w >= NN) return;
    const float* row = g_g1 + w * HH;
    float s = 0.f;
    for (int k = lane; k < HH; k += 32) s += row[k] * wg2[k];
#pragma unroll
    for (int o = 16; o; o >>= 1) s += __shfl_xor_sync(0xffffffffu, s, o);
    if (lane == 0) {
        float g = s + bg2[0];
        g_gate[w] = g;
        atomicMax(&g_gmax[batch[w]], enc_f(g));
    }
}
__global__ void k_softw(const int* __restrict__ batch) {
    int n = blockIdx.x * blockDim.x + threadIdx.x;
    if (n >= NN) return;
    int b = batch[n];
    float wv = __expf(g_gate[n] - dec_f(g_gmax[b]));
    g_w[n] = wv;
    atomicAdd(&g_wsum[b], wv);
}
__global__ void k_pool(const int* __restrict__ batch) {
    int n = blockIdx.x;
    int d = threadIdx.x;
    if (d >= HH) return;
    int b = batch[n];
    float alpha = g_w[n] / g_wsum[b];
    atomicAdd(&g_pooled[b * HH + d], alpha * g_h[n * HH + d]);
}

// ================= FC via fp16 mma.sync m16n8k16 (native HMMA path) =================
#define FKH 120
#define FC_SMEM_H (128 * FKH * 2 * 2 + 512)   /* 61952 bytes */

__global__ void __launch_bounds__(256)
k_fc(const float* __restrict__ pooled, const float* __restrict__ W,
     const float* __restrict__ bias, float* __restrict__ C) {
    extern __shared__ __align__(16) char smraw[];
    __half*   BsH  = (__half*)smraw;
    uint32_t* Bs32 = (uint32_t*)smraw;
    uint32_t* As32 = (uint32_t*)(smraw + 128 * FKH * 2);
    float*    biasS = (float*)(smraw + 2 * 128 * FKH * 2);
    int tid = threadIdx.x;
    int lane = tid & 31, wid = tid >> 5;
    int n0 = blockIdx.x * 128;
    int m_begin = blockIdx.y * 16;

    for (int i = tid; i < 2 * 128 * (FKH / 2); i += 256) ((uint32_t*)smraw)[i] = 0u;
    if (tid < 128) biasS[tid] = (n0 + tid < VV) ? bias[n0 + tid] : 0.f;
    __syncthreads();

    for (int i = tid; i < HH * 128; i += 256) {
        int k = i >> 7, n = i & 127;
        int gn = n0 + n;
        if (gn < VV) BsH[n * FKH + k] = __float2half_rn(W[(size_t)k * VV + gn]);
    }

    int wm = wid >> 2, wn = wid & 3;
    int g = lane >> 2, tg = lane & 3;

    for (int it = 0; it < 16; it++) {
        int m0 = (m_begin + it) * 128;
        for (int p = tid; p < 128 * (HH / 2); p += 256) {
            int r = p / (HH / 2), kp = p - r * (HH / 2);
            float2 v = *(const float2*)&pooled[(size_t)(m0 + r) * HH + 2 * kp];
            __half2 h2 = __floats2half2_rn(v.x, v.y);
            As32[r * (FKH / 2) + kp] = *(uint32_t*)&h2;
        }
        __syncthreads();

        float acc[4][4][4];
#pragma unroll
        for (int mi = 0; mi < 4; mi++)
#pragma unroll
            for (int ni = 0; ni < 4; ni++)
#pragma unroll
                for (int j = 0; j < 4; j++) acc[mi][ni][j] = 0.f;

#pragma unroll
        for (int ks = 0; ks < 7; ks++) {
            int kw = ks * 8;
            uint32_t af[4][4], bf[4][2];
#pragma unroll
            for (int mi = 0; mi < 4; mi++) {
                int r0 = wm * 64 + mi * 16 + g;
                const uint32_t* ap = &As32[r0 * 60 + kw + tg];
                af[mi][0] = ap[0];
                af[mi][1] = ap[8 * 60];
                af[mi][2] = ap[4];
                af[mi][3] = ap[8 * 60 + 4];
            }
#pragma unroll
            for (int ni = 0; ni < 4; ni++) {
                int nb = wn * 32 + ni * 8 + g;
                const uint32_t* bp = &Bs32[nb * 60 + kw + tg];
                bf[ni][0] = bp[0];
                bf[ni][1] = bp[4];
            }
#pragma unroll
            for (int mi = 0; mi < 4; mi++)
#pragma unroll
                for (int ni = 0; ni < 4; ni++)
                    mma_16n8k16_f16(acc[mi][ni], af[mi], bf[ni]);
        }

#pragma unroll
        for (int mi = 0; mi < 4; mi++) {
            int r = m0 + wm * 64 + mi * 16 + g;
            size_t rb0 = (size_t)r * VV;
            size_t rb1 = (size_t)(r + 8) * VV;
#pragma unroll
            for (int ni = 0; ni < 4; ni++) {
                int cn = wn * 32 + ni * 8 + 2 * tg;
                int gn = n0 + cn;
                if (gn < VV) {
                    float bx = biasS[cn], by = biasS[cn + 1];
                    *(float2*)&C[rb0 + gn] = make_float2(acc[mi][ni][0] + bx,
                                                         acc[mi][ni][1] + by);
                    *(float2*)&C[rb1 + gn] = make_float2(acc[mi][ni][2] + bx,
                                                         acc[mi][ni][3] + by);
                }
            }
        }
        __syncthreads();
    }
}

// ---------------- launch ----------------
extern "C" void kernel_launch(void* const* d_in, const int* in_sizes, int n_in,
                              void* d_out, int out_size) {
    const float* price    = (const float*)d_in[0];
    const int*   category = (const int*)d_in[1];
    const int*   sub      = (const int*)d_in[2];
    const int*   elem     = (const int*)d_in[3];
    const int*   brand    = (const int*)d_in[4];
    const int*   pid      = (const int*)d_in[5];
    const int*   eidx     = (const int*)d_in[6];
    const int*   batch    = (const int*)d_in[7];
    const float* ecat     = (const float*)d_in[8];
    const float* esub     = (const float*)d_in[9];
    const float* eelem    = (const float*)d_in[10];
    const float* ebrand   = (const float*)d_in[11];
    const float* eitem    = (const float*)d_in[12];
    const float* W_msg    = (const float*)d_in[13];
    const float* b_msg    = (const float*)d_in[14];
    const float* W_ih     = (const float*)d_in[15];
    const float* W_hh     = (const float*)d_in[16];
    const float* b_ih     = (const float*)d_in[17];
    const float* b_hh     = (const float*)d_in[18];
    const float* W_last   = (const float*)d_in[19];
    const float* b_last   = (const float*)d_in[20];
    const float* W_g1     = (const float*)d_in[21];
    const float* b_g1     = (const float*)d_in[22];
    const float* W_g2     = (const float*)d_in[23];
    const float* b_g2     = (const float*)d_in[24];
    const float* W_fc     = (const float*)d_in[25];
    const float* b_fc     = (const float*)d_in[26];
    float* out = (float*)d_out;

    float *p_x, *p_xl, *p_h, *p_msg, *p_gi, *p_gh, *p_last, *p_g1, *p_pooled;
    cudaGetSymbolAddress((void**)&p_x,      g_x);
    cudaGetSymbolAddress((void**)&p_xl,     g_xl);
    cudaGetSymbolAddress((void**)&p_h,      g_h);
    cudaGetSymbolAddress((void**)&p_msg,    g_msg);
    cudaGetSymbolAddress((void**)&p_gi,     g_gi);
    cudaGetSymbolAddress((void**)&p_gh,     g_gh);
    cudaGetSymbolAddress((void**)&p_last,   g_last);
    cudaGetSymbolAddress((void**)&p_g1,     g_g1);
    cudaGetSymbolAddress((void**)&p_pooled, g_pooled);

    cudaFuncSetAttribute(k_fc,     cudaFuncAttributeMaxDynamicSharedMemorySize, FC_SMEM_H);
    cudaFuncSetAttribute(k_hgemm2, cudaFuncAttributeMaxDynamicSharedMemorySize, H2_SMEM);

    // init scratch
    k_init_small<<<(NN + 255) / 256, 256>>>();
    k_zero_big<<<(NN * HH + 255) / 256, 256>>>();

    // node features
    k_gather_x<<<NN, 352>>>(price, category, sub, elem, brand, pid,
                            ecat, esub, eelem, ebrand, eitem);

    // h0 = x @ W_msg + b_msg   (f32x2 SGEMM — K=321 too large for resident split panel)
    {
        dim3 g((HH + 63) / 64, (NN + 127) / 128);
        k_sgemm<<<g, 256>>>(p_x, W_msg, b_msg, p_h, NN, HH, FIN, 0);
    }

    // degrees
    k_deg<<<(EE + 255) / 256, 256>>>(eidx);
    k_dinv<<<(NN + 255) / 256, 256>>>();

    // mean aggregation
    k_scatter<<<EE, 128>>>(eidx);
    k_scale_msg<<<(NN * HH + 255) / 256, 256>>>();

    // GRU gates (split-fp16 HMMA, B-resident)
    {
        dim3 g((3 * HH + 127) / 128, 160);
        k_hgemm2<<<g, 256, H2_SMEM>>>(p_msg, W_ih, b_ih, p_gi, NN, 3 * HH, HH, 0);
        k_hgemm2<<<g, 256, H2_SMEM>>>(p_h,   W_hh, b_hh, p_gh, NN, 3 * HH, HH, 0);
    }
    k_gru<<<(NN * HH + 255) / 256, 256>>>();

    // last node per session
    k_lastidx<<<(NN + 255) / 256, 256>>>(batch);
    k_gather_xl<<<SS, 352>>>();
    {
        dim3 g((HH + 63) / 64, (SS + 127) / 128);
        k_sgemm<<<g, 256>>>(p_xl, W_last, b_last, p_last, SS, HH, FIN, 0);
    }
    k_addlast<<<(NN * HH + 255) / 256, 256>>>(batch);

    // attention gate MLP (split-fp16 HMMA, relu)
    {
        dim3 g(1, 160);
        k_hgemm2<<<g, 256, H2_SMEM>>>(p_h, W_g1, b_g1, p_g1, NN, HH, HH, 1);
    }
    k_gate<<<(NN * 32 + 255) / 256, 256>>>(W_g2, b_g2, batch);
    k_softw<<<(NN + 255) / 256, 256>>>(batch);
    k_pool<<<NN, 128>>>(batch);

    // final scoring: fp16 mma.sync m16n8k16
    {
        dim3 g((VV + 127) / 128, 2);
        k_fc<<<g, 256, FC_SMEM_H>>>(p_pooled, W_fc, b_fc, out);
    }
}

// round 14
// speedup vs baseline: 1.2073x; 1.2069x over previous
#include <cuda_runtime.h>
#include <cuda_fp16.h>
#include <math.h>
#include <stdint.h>

#define NN   40960
#define SS   4096
#define EE   81920
#define DD   64
#define HH   100
#define FIN  321
#define VV   50000

// ---------------- scratch (device globals; no allocation allowed) ----------------
__device__ float    g_x[NN * FIN];
__device__ float    g_xl[SS * FIN];
__device__ float    g_h[NN * HH];
__device__ float    g_msg[NN * HH];
__device__ float    g_gi[NN * 3 * HH];
__device__ float    g_gh[NN * 3 * HH];
__device__ int      g_deg[NN];
__device__ float    g_dinv[NN];
__device__ int      g_lastidx[SS];
__device__ float    g_last[SS * HH];
__device__ float    g_g1[NN * HH];
__device__ float    g_gate[NN];
__device__ float    g_w[NN];
__device__ unsigned g_gmax[SS];
__device__ float    g_wsum[SS];
__device__ float    g_pooled[SS * HH];

// ---------------- f32x2 packed-math helpers (Blackwell FFMA2) ----------------
__device__ __forceinline__ unsigned long long f2_pack(float lo, float hi) {
    unsigned long long r;
    asm("mov.b64 %0, {%1, %2};" : "=l"(r) : "f"(lo), "f"(hi));
    return r;
}
__device__ __forceinline__ float2 f2_unpack(unsigned long long v) {
    float lo, hi;
    asm("mov.b64 {%0, %1}, %2;" : "=f"(lo), "=f"(hi) : "l"(v));
    return make_float2(lo, hi);
}
__device__ __forceinline__ unsigned long long f2_fma(unsigned long long a,
                                                     unsigned long long b,
                                                     unsigned long long c) {
    asm("fma.rn.f32x2 %0, %1, %2, %3;" : "=l"(c) : "l"(a), "l"(b), "l"(c));
    return c;
}

// ---------------- fp16 mma.sync (plain HMMA path) ----------------
__device__ __forceinline__ void mma_16n8k16_f16(float* d,
                                                const uint32_t* a, const uint32_t* b) {
    asm volatile(
        "mma.sync.aligned.m16n8k16.row.col.f32.f16.f16.f32 "
        "{%0, %1, %2, %3}, {%4, %5, %6, %7}, {%8, %9}, {%0, %1, %2, %3};"
        : "+f"(d[0]), "+f"(d[1]), "+f"(d[2]), "+f"(d[3])
        : "r"(a[0]), "r"(a[1]), "r"(a[2]), "r"(a[3]), "r"(b[0]), "r"(b[1]));
}

// ---------------- helpers ----------------
__device__ __forceinline__ unsigned enc_f(float f) {
    unsigned u = __float_as_uint(f);
    return (u & 0x80000000u) ? ~u : (u | 0x80000000u);
}
__device__ __forceinline__ float dec_f(unsigned e) {
    return (e & 0x80000000u) ? __uint_as_float(e ^ 0x80000000u) : __uint_as_float(~e);
}
__device__ __forceinline__ float fast_sigmoid(float x) {
    return 1.f / (1.f + __expf(-x));
}
__device__ __forceinline__ float fast_tanh(float x) {
    float t = __expf(-2.f * fabsf(x));
    float y = (1.f - t) / (1.f + t);
    return copysignf(y, x);
}

// ---------------- init / zero ----------------
__global__ void k_init_small() {
    int i = blockIdx.x * blockDim.x + threadIdx.x;
    if (i < NN) g_deg[i] = 0;
    if (i < SS) { g_lastidx[i] = -1; g_gmax[i] = 0u; g_wsum[i] = 0.f; }
}
__global__ void k_zero_big() {
    int i = blockIdx.x * blockDim.x + threadIdx.x;
    if (i < NN * HH) g_msg[i] = 0.f;
    if (i < SS * HH) g_pooled[i] = 0.f;
}

// ---------------- node feature gather: x[n, 0..320] ----------------
__global__ void k_gather_x(const float* __restrict__ price,
                           const int* __restrict__ cat, const int* __restrict__ sub,
                           const int* __restrict__ elem, const int* __restrict__ brand,
                           const int* __restrict__ pid,
                           const float* __restrict__ ecat, const float* __restrict__ esub,
                           const float* __restrict__ eelem, const float* __restrict__ ebrand,
                           const float* __restrict__ eitem) {
    int n = blockIdx.x;
    int j = threadIdx.x;
    if (j >= FIN) return;
    float v;
    if (j == 0) {
        v = price[n];
    } else {
        int s = (j - 1) >> 6;
        int o = (j - 1) & 63;
        const float* tab;
        int idx;
        switch (s) {
            case 0:  tab = ecat;   idx = cat[n];   break;
            case 1:  tab = esub;   idx = sub[n];   break;
            case 2:  tab = eelem;  idx = elem[n];  break;
            case 3:  tab = ebrand; idx = brand[n]; break;
            default: tab = eitem;  idx = pid[n];   break;
        }
        v = tab[idx * DD + o];
    }
    g_x[n * FIN + j] = v;
}

// ---------------- tiled SGEMM: C = A[M,K] @ B[K,Nn] + bias, optional relu ----------------
// 128x64 block tile, 8x4 per-thread register tile, f32x2 packed FMA.
// A stored pre-duplicated as (a,a) 64-bit words: no packs in the inner loop.
// NOTE: all hot indices 32-bit (size_t in hot path cost 16 regs / 30% occ in R13).
__global__ void k_sgemm(const float* __restrict__ A, const float* __restrict__ B,
                        const float* __restrict__ bias, float* __restrict__ C,
                        int M, int Nn, int K, int relu) {
    __shared__ unsigned long long As2[128][17];
    __shared__ float Bs[16][64];
    int tid = threadIdx.x;
    int tx = tid & 15, ty = tid >> 4;     // tx: 4 cols each, ty: 8 rows each
    int m0 = blockIdx.y * 128, n0 = blockIdx.x * 64;

    unsigned long long acc2[8][2];
#pragma unroll
    for (int i = 0; i < 8; i++) { acc2[i][0] = 0ull; acc2[i][1] = 0ull; }

    for (int k0 = 0; k0 < K; k0 += 16) {
        for (int i = tid; i < 128 * 16; i += 256) {
            int mi = i >> 4, ki = i & 15;
            int m = m0 + mi, k = k0 + ki;
            float a = (m < M && k < K) ? A[m * K + k] : 0.f;
            As2[mi][ki] = f2_pack(a, a);
        }
        for (int i = tid; i < 16 * 64; i += 256) {
            int ki = i >> 6, ni = i & 63;
            int k = k0 + ki, n = n0 + ni;
            Bs[ki][ni] = (k < K && n < Nn) ? B[k * Nn + n] : 0.f;
        }
        __syncthreads();
#pragma unroll
        for (int k = 0; k < 16; k++) {
            ulonglong2 b2 = *(const ulonglong2*)&Bs[k][tx * 4];
#pragma unroll
            for (int i = 0; i < 8; i++) {
                unsigned long long ap = As2[ty * 8 + i][k];
                acc2[i][0] = f2_fma(ap, b2.x, acc2[i][0]);
                acc2[i][1] = f2_fma(ap, b2.y, acc2[i][1]);
            }
        }
        __syncthreads();
    }

#pragma unroll
    for (int i = 0; i < 8; i++) {
        int m = m0 + ty * 8 + i;
        if (m >= M) continue;
        float2 p0 = f2_unpack(acc2[i][0]);
        float2 p1 = f2_unpack(acc2[i][1]);
        float vals[4] = {p0.x, p0.y, p1.x, p1.y};
#pragma unroll
        for (int j = 0; j < 4; j++) {
            int n = n0 + tx * 4 + j;
            if (n >= Nn) continue;
            float v = vals[j] + bias[n];
            if (relu) v = fmaxf(v, 0.f);
            C[m * Nn + n] = v;
        }
    }
}

// ---------------- degree + inverse ----------------
__global__ void k_deg(const int* __restrict__ eidx) {
    int e = blockIdx.x * blockDim.x + threadIdx.x;
    if (e < EE) atomicAdd(&g_deg[eidx[EE + e]], 1);
}
__global__ void k_dinv() {
    int n = blockIdx.x * blockDim.x + threadIdx.x;
    if (n < NN) g_dinv[n] = (g_deg[n] > 0) ? (1.f / (float)g_deg[n]) : 0.f;
}

// ---------------- edge scatter: msg[dst] += h[src] * dinv[dst]  (mean fused) ----------------
__global__ void k_scatter(const int* __restrict__ eidx) {
    int e = blockIdx.x;
    int d = threadIdx.x;
    if (d >= HH) return;
    int s = eidx[e];
    int t = eidx[EE + e];
    atomicAdd(&g_msg[t * HH + d], g_h[s * HH + d] * g_dinv[t]);
}

// ---------------- GRU cell elementwise, fused with last-node add ----------------
__global__ void k_gru(const int* __restrict__ batch) {
    int i = blockIdx.x * blockDim.x + threadIdx.x;
    if (i >= NN * HH) return;
    int n = i / HH, j = i % HH;
    const float* gi = g_gi + n * 3 * HH;
    const float* gh = g_gh + n * 3 * HH;
    float r  = fast_sigmoid(gi[j] + gh[j]);
    float z  = fast_sigmoid(gi[HH + j] + gh[HH + j]);
    float nn = fast_tanh(gi[2 * HH + j] + r * gh[2 * HH + j]);
    float h  = g_h[i];
    g_h[i] = (1.f - z) * nn + z * h + g_last[batch[n] * HH + j];
}

// ---------------- last index per session + gather ----------------
__global__ void k_lastidx(const int* __restrict__ batch) {
    int n = blockIdx.x * blockDim.x + threadIdx.x;
    if (n < NN) atomicMax(&g_lastidx[batch[n]], n);
}
__global__ void k_gather_xl() {
    int s = blockIdx.x;
    int j = threadIdx.x;
    if (j >= FIN) return;
    g_xl[s * FIN + j] = g_x[g_lastidx[s] * FIN + j];
}

// ---------------- attention gate ----------------
__global__ void k_gate(const float* __restrict__ wg2, const float* __restrict__ bg2,
                       const int* __restrict__ batch) {
    int w = (blockIdx.x * blockDim.x + threadIdx.x) >> 5;
    int lane = threadIdx.x & 31;
    if (w >= NN) return;
    const float* row = g_g1 + w * HH;
    float s = 0.f;
    for (int k = lane; k < HH; k += 32) s += row[k] * wg2[k];
#pragma unroll
    for (int o = 16; o; o >>= 1) s += __shfl_xor_sync(0xffffffffu, s, o);
    if (lane == 0) {
        float g = s + bg2[0];
        g_gate[w] = g;
        atomicMax(&g_gmax[batch[w]], enc_f(g));
    }
}
__global__ void k_softw(const int* __restrict__ batch) {
    int n = blockIdx.x * blockDim.x + threadIdx.x;
    if (n >= NN) return;
    int b = batch[n];
    float wv = __expf(g_gate[n] - dec_f(g_gmax[b]));
    g_w[n] = wv;
    atomicAdd(&g_wsum[b], wv);
}
__global__ void k_pool(const int* __restrict__ batch) {
    int n = blockIdx.x;
    int d = threadIdx.x;
    if (d >= HH) return;
    int b = batch[n];
    float alpha = g_w[n] / g_wsum[b];
    atomicAdd(&g_pooled[b * HH + d], alpha * g_h[n * HH + d]);
}

// ================= FC via fp16 mma.sync m16n8k16 (native HMMA path) =================
// out[4096,50000] = pooled @ W_fc + b_fc  (fp16 inputs, fp32 accumulate)
#define FKH 120
#define FC_SMEM_H (128 * FKH * 2 * 2 + 512)   /* 61952 bytes */

__global__ void __launch_bounds__(256)
k_fc(const float* __restrict__ pooled, const float* __restrict__ W,
     const float* __restrict__ bias, float* __restrict__ C) {
    extern __shared__ __align__(16) char smraw[];
    __half*   BsH  = (__half*)smraw;                       // [128][FKH]
    uint32_t* Bs32 = (uint32_t*)smraw;                     // word view, stride 60
    uint32_t* As32 = (uint32_t*)(smraw + 128 * FKH * 2);   // word view, stride 60
    float*    biasS = (float*)(smraw + 2 * 128 * FKH * 2); // [128]
    int tid = threadIdx.x;
    int lane = tid & 31, wid = tid >> 5;
    int n0 = blockIdx.x * 128;
    int m_begin = blockIdx.y * 16;

    for (int i = tid; i < 2 * 128 * (FKH / 2); i += 256) ((uint32_t*)smraw)[i] = 0u;
    if (tid < 128) biasS[tid] = (n0 + tid < VV) ? bias[n0 + tid] : 0.f;
    __syncthreads();

    for (int i = tid; i < HH * 128; i += 256) {
        int k = i >> 7, n = i & 127;
        int gn = n0 + n;
        if (gn < VV) BsH[n * FKH + k] = __float2half_rn(W[(size_t)k * VV + gn]);
    }

    int wm = wid >> 2, wn = wid & 3;
    int g = lane >> 2, tg = lane & 3;

    for (int it = 0; it < 16; it++) {
        int m0 = (m_begin + it) * 128;
        for (int p = tid; p < 128 * (HH / 2); p += 256) {
            int r = p / (HH / 2), kp = p - r * (HH / 2);
            float2 v = *(const float2*)&pooled[(m0 + r) * HH + 2 * kp];
            __half2 h2 = __floats2half2_rn(v.x, v.y);
            As32[r * (FKH / 2) + kp] = *(uint32_t*)&h2;
        }
        __syncthreads();

        float acc[4][4][4];
#pragma unroll
        for (int mi = 0; mi < 4; mi++)
#pragma unroll
            for (int ni = 0; ni < 4; ni++)
#pragma unroll
                for (int j = 0; j < 4; j++) acc[mi][ni][j] = 0.f;

#pragma unroll
        for (int ks = 0; ks < 7; ks++) {
            int kw = ks * 8;
            uint32_t af[4][4], bf[4][2];
#pragma unroll
            for (int mi = 0; mi < 4; mi++) {
                int r0 = wm * 64 + mi * 16 + g;
                const uint32_t* ap = &As32[r0 * 60 + kw + tg];
                af[mi][0] = ap[0];
                af[mi][1] = ap[8 * 60];
                af[mi][2] = ap[4];
                af[mi][3] = ap[8 * 60 + 4];
            }
#pragma unroll
            for (int ni = 0; ni < 4; ni++) {
                int nb = wn * 32 + ni * 8 + g;
                const uint32_t* bp = &Bs32[nb * 60 + kw + tg];
                bf[ni][0] = bp[0];
                bf[ni][1] = bp[4];
            }
#pragma unroll
            for (int mi = 0; mi < 4; mi++)
#pragma unroll
                for (int ni = 0; ni < 4; ni++)
                    mma_16n8k16_f16(acc[mi][ni], af[mi], bf[ni]);
        }

#pragma unroll
        for (int mi = 0; mi < 4; mi++) {
            int r = m0 + wm * 64 + mi * 16 + g;
            size_t rb0 = (size_t)r * VV;
            size_t rb1 = (size_t)(r + 8) * VV;
#pragma unroll
            for (int ni = 0; ni < 4; ni++) {
                int cn = wn * 32 + ni * 8 + 2 * tg;
                int gn = n0 + cn;
                if (gn < VV) {
                    float bx = biasS[cn], by = biasS[cn + 1];
                    *(float2*)&C[rb0 + gn] = make_float2(acc[mi][ni][0] + bx,
                                                         acc[mi][ni][1] + by);
                    *(float2*)&C[rb1 + gn] = make_float2(acc[mi][ni][2] + bx,
                                                         acc[mi][ni][3] + by);
                }
            }
        }
        __syncthreads();
    }
}

// ---------------- launch ----------------
extern "C" void kernel_launch(void* const* d_in, const int* in_sizes, int n_in,
                              void* d_out, int out_size) {
    const float* price    = (const float*)d_in[0];
    const int*   category = (const int*)d_in[1];
    const int*   sub      = (const int*)d_in[2];
    const int*   elem     = (const int*)d_in[3];
    const int*   brand    = (const int*)d_in[4];
    const int*   pid      = (const int*)d_in[5];
    const int*   eidx     = (const int*)d_in[6];
    const int*   batch    = (const int*)d_in[7];
    const float* ecat     = (const float*)d_in[8];
    const float* esub     = (const float*)d_in[9];
    const float* eelem    = (const float*)d_in[10];
    const float* ebrand   = (const float*)d_in[11];
    const float* eitem    = (const float*)d_in[12];
    const float* W_msg    = (const float*)d_in[13];
    const float* b_msg    = (const float*)d_in[14];
    const float* W_ih     = (const float*)d_in[15];
    const float* W_hh     = (const float*)d_in[16];
    const float* b_ih     = (const float*)d_in[17];
    const float* b_hh     = (const float*)d_in[18];
    const float* W_last   = (const float*)d_in[19];
    const float* b_last   = (const float*)d_in[20];
    const float* W_g1     = (const float*)d_in[21];
    const float* b_g1     = (const float*)d_in[22];
    const float* W_g2     = (const float*)d_in[23];
    const float* b_g2     = (const float*)d_in[24];
    const float* W_fc     = (const float*)d_in[25];
    const float* b_fc     = (const float*)d_in[26];
    float* out = (float*)d_out;

    float *p_x, *p_xl, *p_h, *p_msg, *p_gi, *p_gh, *p_last, *p_g1, *p_pooled;
    cudaGetSymbolAddress((void**)&p_x,      g_x);
    cudaGetSymbolAddress((void**)&p_xl,     g_xl);
    cudaGetSymbolAddress((void**)&p_h,      g_h);
    cudaGetSymbolAddress((void**)&p_msg,    g_msg);
    cudaGetSymbolAddress((void**)&p_gi,     g_gi);
    cudaGetSymbolAddress((void**)&p_gh,     g_gh);
    cudaGetSymbolAddress((void**)&p_last,   g_last);
    cudaGetSymbolAddress((void**)&p_g1,     g_g1);
    cudaGetSymbolAddress((void**)&p_pooled, g_pooled);

    cudaFuncSetAttribute(k_fc, cudaFuncAttributeMaxDynamicSharedMemorySize, FC_SMEM_H);

    // init scratch
    k_init_small<<<(NN + 255) / 256, 256>>>();
    k_zero_big<<<(NN * HH + 255) / 256, 256>>>();

    // node features
    k_gather_x<<<NN, 352>>>(price, category, sub, elem, brand, pid,
                            ecat, esub, eelem, ebrand, eitem);

    // h0 = x @ W_msg + b_msg
    {
        dim3 g((HH + 63) / 64, (NN + 127) / 128);
        k_sgemm<<<g, 256>>>(p_x, W_msg, b_msg, p_h, NN, HH, FIN, 0);
    }

    // last-node features (independent of GRU chain; needed by fused k_gru)
    k_lastidx<<<(NN + 255) / 256, 256>>>(batch);
    k_gather_xl<<<SS, 352>>>();
    {
        dim3 g((HH + 63) / 64, (SS + 127) / 128);
        k_sgemm<<<g, 256>>>(p_xl, W_last, b_last, p_last, SS, HH, FIN, 0);
    }

    // degrees
    k_deg<<<(EE + 255) / 256, 256>>>(eidx);
    k_dinv<<<(NN + 255) / 256, 256>>>();

    // mean aggregation (dinv fused into scatter)
    k_scatter<<<EE, 128>>>(eidx);

    // GRU gates
    {
        dim3 g((3 * HH + 63) / 64, (NN + 127) / 128);
        k_sgemm<<<g, 256>>>(p_msg, W_ih, b_ih, p_gi, NN, 3 * HH, HH, 0);
        k_sgemm<<<g, 256>>>(p_h,   W_hh, b_hh, p_gh, NN, 3 * HH, HH, 0);
    }
    // GRU + last-node add fused
    k_gru<<<(NN * HH + 255) / 256, 256>>>(batch);

    // attention gate MLP
    {
        dim3 g((HH + 63) / 64, (NN + 127) / 128);
        k_sgemm<<<g, 256>>>(p_h, W_g1, b_g1, p_g1, NN, HH, HH, 1);
    }
    k_gate<<<(NN * 32 + 255) / 256, 256>>>(W_g2, b_g2, batch);
    k_softw<<<(NN + 255) / 256, 256>>>(batch);
    k_pool<<<NN, 128>>>(batch);

    // final scoring: fp16 mma.sync m16n8k16
    {
        dim3 g((VV + 127) / 128, 2);
        k_fc<<<g, 256, FC_SMEM_H>>>(p_pooled, W_fc, b_fc, out);
    }
}

// round 15
// speedup vs baseline: 1.3243x; 1.0969x over previous
#include <cuda_runtime.h>
#include <cuda_fp16.h>
#include <math.h>
#include <stdint.h>

#define NN   40960
#define SS   4096
#define EE   81920
#define DD   64
#define HH   100
#define FIN  321
#define VV   50000

// ---------------- scratch (device globals; no allocation allowed) ----------------
__device__ float    g_x[NN * FIN];
__device__ float    g_xl[SS * FIN];
__device__ float    g_h[NN * HH];
__device__ float    g_msg[NN * HH];
__device__ float    g_gi[NN * 3 * HH];
__device__ float    g_gh[NN * 3 * HH];
__device__ int      g_deg[NN];
__device__ float    g_dinv[NN];
__device__ int      g_lastidx[SS];
__device__ float    g_last[SS * HH];
__device__ float    g_g1[NN * HH];
__device__ float    g_gate[NN];
__device__ float    g_w[NN];
__device__ unsigned g_gmax[SS];
__device__ float    g_wsum[SS];
__device__ float    g_pooled[SS * HH];

// ---------------- f32x2 packed-math helpers (Blackwell FFMA2) ----------------
__device__ __forceinline__ unsigned long long f2_pack(float lo, float hi) {
    unsigned long long r;
    asm("mov.b64 %0, {%1, %2};" : "=l"(r) : "f"(lo), "f"(hi));
    return r;
}
__device__ __forceinline__ float2 f2_unpack(unsigned long long v) {
    float lo, hi;
    asm("mov.b64 {%0, %1}, %2;" : "=f"(lo), "=f"(hi) : "l"(v));
    return make_float2(lo, hi);
}
__device__ __forceinline__ unsigned long long f2_fma(unsigned long long a,
                                                     unsigned long long b,
                                                     unsigned long long c) {
    asm("fma.rn.f32x2 %0, %1, %2, %3;" : "=l"(c) : "l"(a), "l"(b), "l"(c));
    return c;
}

// ---------------- fp16 mma.sync (plain HMMA path) ----------------
__device__ __forceinline__ void mma_16n8k16_f16(float* d,
                                                const uint32_t* a, const uint32_t* b) {
    asm volatile(
        "mma.sync.aligned.m16n8k16.row.col.f32.f16.f16.f32 "
        "{%0, %1, %2, %3}, {%4, %5, %6, %7}, {%8, %9}, {%0, %1, %2, %3};"
        : "+f"(d[0]), "+f"(d[1]), "+f"(d[2]), "+f"(d[3])
        : "r"(a[0]), "r"(a[1]), "r"(a[2]), "r"(a[3]), "r"(b[0]), "r"(b[1]));
}

// ---------------- helpers ----------------
__device__ __forceinline__ unsigned enc_f(float f) {
    unsigned u = __float_as_uint(f);
    return (u & 0x80000000u) ? ~u : (u | 0x80000000u);
}
__device__ __forceinline__ float dec_f(unsigned e) {
    return (e & 0x80000000u) ? __uint_as_float(e ^ 0x80000000u) : __uint_as_float(~e);
}
__device__ __forceinline__ float fast_sigmoid(float x) {
    return 1.f / (1.f + __expf(-x));
}
__device__ __forceinline__ float fast_tanh(float x) {
    float t = __expf(-2.f * fabsf(x));
    float y = (1.f - t) / (1.f + t);
    return copysignf(y, x);
}

// ---------------- init / zero ----------------
__global__ void k_init_small() {
    int i = blockIdx.x * blockDim.x + threadIdx.x;
    if (i < NN) g_deg[i] = 0;
    if (i < SS) { g_lastidx[i] = -1; g_gmax[i] = 0u; g_wsum[i] = 0.f; }
}
__global__ void k_zero_big() {
    int i = blockIdx.x * blockDim.x + threadIdx.x;
    if (i < NN * HH) g_msg[i] = 0.f;
    if (i < SS * HH) g_pooled[i] = 0.f;
}

// ---------------- node feature gather: x[n, 0..320] ----------------
__global__ void k_gather_x(const float* __restrict__ price,
                           const int* __restrict__ cat, const int* __restrict__ sub,
                           const int* __restrict__ elem, const int* __restrict__ brand,
                           const int* __restrict__ pid,
                           const float* __restrict__ ecat, const float* __restrict__ esub,
                           const float* __restrict__ eelem, const float* __restrict__ ebrand,
                           const float* __restrict__ eitem) {
    int n = blockIdx.x;
    int j = threadIdx.x;
    if (j >= FIN) return;
    float v;
    if (j == 0) {
        v = price[n];
    } else {
        int s = (j - 1) >> 6;
        int o = (j - 1) & 63;
        const float* tab;
        int idx;
        switch (s) {
            case 0:  tab = ecat;   idx = cat[n];   break;
            case 1:  tab = esub;   idx = sub[n];   break;
            case 2:  tab = eelem;  idx = elem[n];  break;
            case 3:  tab = ebrand; idx = brand[n]; break;
            default: tab = eitem;  idx = pid[n];   break;
        }
        v = tab[idx * DD + o];
    }
    g_x[n * FIN + j] = v;
}

// ---------------- tiled SGEMM: C = A[M,K] @ B[K,Nn] + bias, optional relu ----------------
// 128x64 block tile, 8x4 per-thread register tile, f32x2 packed FMA.
// EXACT R10 configuration (measured 161us on W_msg) — pack-in-loop, float As.
__global__ void k_sgemm(const float* __restrict__ A, const float* __restrict__ B,
                        const float* __restrict__ bias, float* __restrict__ C,
                        int M, int Nn, int K, int relu) {
    __shared__ float As[128][17];
    __shared__ float Bs[16][64];
    int tid = threadIdx.x;
    int tx = tid & 15, ty = tid >> 4;     // tx: 4 cols each, ty: 8 rows each
    int m0 = blockIdx.y * 128, n0 = blockIdx.x * 64;

    unsigned long long acc2[8][2];
#pragma unroll
    for (int i = 0; i < 8; i++) { acc2[i][0] = 0ull; acc2[i][1] = 0ull; }

    for (int k0 = 0; k0 < K; k0 += 16) {
        for (int i = tid; i < 128 * 16; i += 256) {
            int mi = i >> 4, ki = i & 15;
            int m = m0 + mi, k = k0 + ki;
            As[mi][ki] = (m < M && k < K) ? A[m * K + k] : 0.f;
        }
        for (int i = tid; i < 16 * 64; i += 256) {
            int ki = i >> 6, ni = i & 63;
            int k = k0 + ki, n = n0 + ni;
            Bs[ki][ni] = (k < K && n < Nn) ? B[k * Nn + n] : 0.f;
        }
        __syncthreads();
#pragma unroll
        for (int k = 0; k < 16; k++) {
            ulonglong2 b2 = *(const ulonglong2*)&Bs[k][tx * 4];
#pragma unroll
            for (int i = 0; i < 8; i++) {
                float a = As[ty * 8 + i][k];
                unsigned long long ap = f2_pack(a, a);
                acc2[i][0] = f2_fma(ap, b2.x, acc2[i][0]);
                acc2[i][1] = f2_fma(ap, b2.y, acc2[i][1]);
            }
        }
        __syncthreads();
    }

#pragma unroll
    for (int i = 0; i < 8; i++) {
        int m = m0 + ty * 8 + i;
        if (m >= M) continue;
        float2 p0 = f2_unpack(acc2[i][0]);
        float2 p1 = f2_unpack(acc2[i][1]);
        float vals[4] = {p0.x, p0.y, p1.x, p1.y};
#pragma unroll
        for (int j = 0; j < 4; j++) {
            int n = n0 + tx * 4 + j;
            if (n >= Nn) continue;
            float v = vals[j] + bias[n];
            if (relu) v = fmaxf(v, 0.f);
            C[m * Nn + n] = v;
        }
    }
}

// ---------------- degree + inverse ----------------
__global__ void k_deg(const int* __restrict__ eidx) {
    int e = blockIdx.x * blockDim.x + threadIdx.x;
    if (e < EE) atomicAdd(&g_deg[eidx[EE + e]], 1);
}
__global__ void k_dinv() {
    int n = blockIdx.x * blockDim.x + threadIdx.x;
    if (n < NN) g_dinv[n] = (g_deg[n] > 0) ? (1.f / (float)g_deg[n]) : 0.f;
}

// ---------------- edge scatter: msg[dst] += h[src] * dinv[dst]  (mean fused) ----------------
__global__ void k_scatter(const int* __restrict__ eidx) {
    int e = blockIdx.x;
    int d = threadIdx.x;
    if (d >= HH) return;
    int s = eidx[e];
    int t = eidx[EE + e];
    atomicAdd(&g_msg[t * HH + d], g_h[s * HH + d] * g_dinv[t]);
}

// ---------------- GRU cell elementwise, fused with last-node add ----------------
__global__ void k_gru(const int* __restrict__ batch) {
    int i = blockIdx.x * blockDim.x + threadIdx.x;
    if (i >= NN * HH) return;
    int n = i / HH, j = i % HH;
    const float* gi = g_gi + n * 3 * HH;
    const float* gh = g_gh + n * 3 * HH;
    float r  = fast_sigmoid(gi[j] + gh[j]);
    float z  = fast_sigmoid(gi[HH + j] + gh[HH + j]);
    float nn = fast_tanh(gi[2 * HH + j] + r * gh[2 * HH + j]);
    float h  = g_h[i];
    g_h[i] = (1.f - z) * nn + z * h + g_last[batch[n] * HH + j];
}

// ---------------- last index per session + gather ----------------
__global__ void k_lastidx(const int* __restrict__ batch) {
    int n = blockIdx.x * blockDim.x + threadIdx.x;
    if (n < NN) atomicMax(&g_lastidx[batch[n]], n);
}
__global__ void k_gather_xl() {
    int s = blockIdx.x;
    int j = threadIdx.x;
    if (j >= FIN) return;
    g_xl[s * FIN + j] = g_x[g_lastidx[s] * FIN + j];
}

// ---------------- attention gate ----------------
__global__ void k_gate(const float* __restrict__ wg2, const float* __restrict__ bg2,
                       const int* __restrict__ batch) {
    int w = (blockIdx.x * blockDim.x + threadIdx.x) >> 5;
    int lane = threadIdx.x & 31;
    if (w >= NN) return;
    const float* row = g_g1 + w * HH;
    float s = 0.f;
    for (int k = lane; k < HH; k += 32) s += row[k] * wg2[k];
#pragma unroll
    for (int o = 16; o; o >>= 1) s += __shfl_xor_sync(0xffffffffu, s, o);
    if (lane == 0) {
        float g = s + bg2[0];
        g_gate[w] = g;
        atomicMax(&g_gmax[batch[w]], enc_f(g));
    }
}
__global__ void k_softw(const int* __restrict__ batch) {
    int n = blockIdx.x * blockDim.x + threadIdx.x;
    if (n >= NN) return;
    int b = batch[n];
    float wv = __expf(g_gate[n] - dec_f(g_gmax[b]));
    g_w[n] = wv;
    atomicAdd(&g_wsum[b], wv);
}
__global__ void k_pool(const int* __restrict__ batch) {
    int n = blockIdx.x;
    int d = threadIdx.x;
    if (d >= HH) return;
    int b = batch[n];
    float alpha = g_w[n] / g_wsum[b];
    atomicAdd(&g_pooled[b * HH + d], alpha * g_h[n * HH + d]);
}

// ================= FC via fp16 mma.sync m16n8k16 (native HMMA path) =================
// out[4096,50000] = pooled @ W_fc + b_fc  (fp16 inputs, fp32 accumulate)
#define FKH 120
#define FC_SMEM_H (128 * FKH * 2 * 2 + 512)   /* 61952 bytes */

__global__ void __launch_bounds__(256)
k_fc(const float* __restrict__ pooled, const float* __restrict__ W,
     const float* __restrict__ bias, float* __restrict__ C) {
    extern __shared__ __align__(16) char smraw[];
    __half*   BsH  = (__half*)smraw;                       // [128][FKH]
    uint32_t* Bs32 = (uint32_t*)smraw;                     // word view, stride 60
    uint32_t* As32 = (uint32_t*)(smraw + 128 * FKH * 2);   // word view, stride 60
    float*    biasS = (float*)(smraw + 2 * 128 * FKH * 2); // [128]
    int tid = threadIdx.x;
    int lane = tid & 31, wid = tid >> 5;
    int n0 = blockIdx.x * 128;
    int m_begin = blockIdx.y * 16;

    for (int i = tid; i < 2 * 128 * (FKH / 2); i += 256) ((uint32_t*)smraw)[i] = 0u;
    if (tid < 128) biasS[tid] = (n0 + tid < VV) ? bias[n0 + tid] : 0.f;
    __syncthreads();

    for (int i = tid; i < HH * 128; i += 256) {
        int k = i >> 7, n = i & 127;
        int gn = n0 + n;
        if (gn < VV) BsH[n * FKH + k] = __float2half_rn(W[(size_t)k * VV + gn]);
    }

    int wm = wid >> 2, wn = wid & 3;
    int g = lane >> 2, tg = lane & 3;

    for (int it = 0; it < 16; it++) {
        int m0 = (m_begin + it) * 128;
        for (int p = tid; p < 128 * (HH / 2); p += 256) {
            int r = p / (HH / 2), kp = p - r * (HH / 2);
            float2 v = *(const float2*)&pooled[(m0 + r) * HH + 2 * kp];
            __half2 h2 = __floats2half2_rn(v.x, v.y);
            As32[r * (FKH / 2) + kp] = *(uint32_t*)&h2;
        }
        __syncthreads();

        float acc[4][4][4];
#pragma unroll
        for (int mi = 0; mi < 4; mi++)
#pragma unroll
            for (int ni = 0; ni < 4; ni++)
#pragma unroll
                for (int j = 0; j < 4; j++) acc[mi][ni][j] = 0.f;

#pragma unroll
        for (int ks = 0; ks < 7; ks++) {
            int kw = ks * 8;
            uint32_t af[4][4], bf[4][2];
#pragma unroll
            for (int mi = 0; mi < 4; mi++) {
                int r0 = wm * 64 + mi * 16 + g;
                const uint32_t* ap = &As32[r0 * 60 + kw + tg];
                af[mi][0] = ap[0];
                af[mi][1] = ap[8 * 60];
                af[mi][2] = ap[4];
                af[mi][3] = ap[8 * 60 + 4];
            }
#pragma unroll
            for (int ni = 0; ni < 4; ni++) {
                int nb = wn * 32 + ni * 8 + g;
                const uint32_t* bp = &Bs32[nb * 60 + kw + tg];
                bf[ni][0] = bp[0];
                bf[ni][1] = bp[4];
            }
#pragma unroll
            for (int mi = 0; mi < 4; mi++)
#pragma unroll
                for (int ni = 0; ni < 4; ni++)
                    mma_16n8k16_f16(acc[mi][ni], af[mi], bf[ni]);
        }

#pragma unroll
        for (int mi = 0; mi < 4; mi++) {
            int r = m0 + wm * 64 + mi * 16 + g;
            size_t rb0 = (size_t)r * VV;
            size_t rb1 = (size_t)(r + 8) * VV;
#pragma unroll
            for (int ni = 0; ni < 4; ni++) {
                int cn = wn * 32 + ni * 8 + 2 * tg;
                int gn = n0 + cn;
                if (gn < VV) {
                    float bx = biasS[cn], by = biasS[cn + 1];
                    *(float2*)&C[rb0 + gn] = make_float2(acc[mi][ni][0] + bx,
                                                         acc[mi][ni][1] + by);
                    *(float2*)&C[rb1 + gn] = make_float2(acc[mi][ni][2] + bx,
                                                         acc[mi][ni][3] + by);
                }
            }
        }
        __syncthreads();
    }
}

// ---------------- launch ----------------
extern "C" void kernel_launch(void* const* d_in, const int* in_sizes, int n_in,
                              void* d_out, int out_size) {
    const float* price    = (const float*)d_in[0];
    const int*   category = (const int*)d_in[1];
    const int*   sub      = (const int*)d_in[2];
    const int*   elem     = (const int*)d_in[3];
    const int*   brand    = (const int*)d_in[4];
    const int*   pid      = (const int*)d_in[5];
    const int*   eidx     = (const int*)d_in[6];
    const int*   batch    = (const int*)d_in[7];
    const float* ecat     = (const float*)d_in[8];
    const float* esub     = (const float*)d_in[9];
    const float* eelem    = (const float*)d_in[10];
    const float* ebrand   = (const float*)d_in[11];
    const float* eitem    = (const float*)d_in[12];
    const float* W_msg    = (const float*)d_in[13];
    const float* b_msg    = (const float*)d_in[14];
    const float* W_ih     = (const float*)d_in[15];
    const float* W_hh     = (const float*)d_in[16];
    const float* b_ih     = (const float*)d_in[17];
    const float* b_hh     = (const float*)d_in[18];
    const float* W_last   = (const float*)d_in[19];
    const float* b_last   = (const float*)d_in[20];
    const float* W_g1     = (const float*)d_in[21];
    const float* b_g1     = (const float*)d_in[22];
    const float* W_g2     = (const float*)d_in[23];
    const float* b_g2     = (const float*)d_in[24];
    const float* W_fc     = (const float*)d_in[25];
    const float* b_fc     = (const float*)d_in[26];
    float* out = (float*)d_out;

    float *p_x, *p_xl, *p_h, *p_msg, *p_gi, *p_gh, *p_last, *p_g1, *p_pooled;
    cudaGetSymbolAddress((void**)&p_x,      g_x);
    cudaGetSymbolAddress((void**)&p_xl,     g_xl);
    cudaGetSymbolAddress((void**)&p_h,      g_h);
    cudaGetSymbolAddress((void**)&p_msg,    g_msg);
    cudaGetSymbolAddress((void**)&p_gi,     g_gi);
    cudaGetSymbolAddress((void**)&p_gh,     g_gh);
    cudaGetSymbolAddress((void**)&p_last,   g_last);
    cudaGetSymbolAddress((void**)&p_g1,     g_g1);
    cudaGetSymbolAddress((void**)&p_pooled, g_pooled);

    cudaFuncSetAttribute(k_fc, cudaFuncAttributeMaxDynamicSharedMemorySize, FC_SMEM_H);

    // init scratch
    k_init_small<<<(NN + 255) / 256, 256>>>();
    k_zero_big<<<(NN * HH + 255) / 256, 256>>>();

    // node features
    k_gather_x<<<NN, 352>>>(price, category, sub, elem, brand, pid,
                            ecat, esub, eelem, ebrand, eitem);

    // h0 = x @ W_msg + b_msg
    {
        dim3 g((HH + 63) / 64, (NN + 127) / 128);
        k_sgemm<<<g, 256>>>(p_x, W_msg, b_msg, p_h, NN, HH, FIN, 0);
    }

    // last-node features (independent of GRU chain; needed by fused k_gru)
    k_lastidx<<<(NN + 255) / 256, 256>>>(batch);
    k_gather_xl<<<SS, 352>>>();
    {
        dim3 g((HH + 63) / 64, (SS + 127) / 128);
        k_sgemm<<<g, 256>>>(p_xl, W_last, b_last, p_last, SS, HH, FIN, 0);
    }

    // degrees
    k_deg<<<(EE + 255) / 256, 256>>>(eidx);
    k_dinv<<<(NN + 255) / 256, 256>>>();

    // mean aggregation (dinv fused into scatter)
    k_scatter<<<EE, 128>>>(eidx);

    // GRU gates
    {
        dim3 g((3 * HH + 63) / 64, (NN + 127) / 128);
        k_sgemm<<<g, 256>>>(p_msg, W_ih, b_ih, p_gi, NN, 3 * HH, HH, 0);
        k_sgemm<<<g, 256>>>(p_h,   W_hh, b_hh, p_gh, NN, 3 * HH, HH, 0);
    }
    // GRU + last-node add fused
    k_gru<<<(NN * HH + 255) / 256, 256>>>(batch);

    // attention gate MLP
    {
        dim3 g((HH + 63) / 64, (NN + 127) / 128);
        k_sgemm<<<g, 256>>>(p_h, W_g1, b_g1, p_g1, NN, HH, HH, 1);
    }
    k_gate<<<(NN * 32 + 255) / 256, 256>>>(W_g2, b_g2, batch);
    k_softw<<<(NN + 255) / 256, 256>>>(batch);
    k_pool<<<NN, 128>>>(batch);

    // final scoring: fp16 mma.sync m16n8k16
    {
        dim3 g((VV + 127) / 128, 2);
        k_fc<<<g, 256, FC_SMEM_H>>>(p_pooled, W_fc, b_fc, out);
    }
}